// round 2
// baseline (speedup 1.0000x reference)
#include <cuda_runtime.h>
#include <cstdint>

// Problem constants (fixed by reference setup_inputs)
#define NTOK 16384
#define DM   1280
#define NH   16
#define HK   80
#define NSEGS 8
#define SEGL 2048

#define NEG_INF (__int_as_float(0xff800000))

// Scratch (allocation-free rule: __device__ globals)
__device__ float g_qkv[(size_t)NTOK * 3 * DM];   // [N][3*1280] : q|k|v, head-major within each
__device__ float g_ao [(size_t)NTOK * DM];       // attention output [N][1280]

// ---------------------------------------------------------------------------
// GEMM with bias: C[M,N] = A[M,Kd] @ B[Kd,N] + bias[N]
// 128x128 tile, BK=8, 256 threads, 8x8 per thread, double-buffered smem.
// All dims are exact multiples (M=16384, N in {3840,1280}, Kd=1280).
// ---------------------------------------------------------------------------
__global__ __launch_bounds__(256) void gemm_bias_kernel(
    const float* __restrict__ A, const float* __restrict__ B,
    const float* __restrict__ bias, float* __restrict__ C,
    int M, int N, int Kd)
{
    __shared__ float As[2][8][128];
    __shared__ float Bs[2][8][128];
    const int tid = threadIdx.x;
    const int bx = blockIdx.x, by = blockIdx.y;

    const int arow = tid >> 1;
    const int acol = (tid & 1) << 2;
    const int brow = tid >> 5;
    const int bcol = (tid & 31) << 2;

    const float* Aptr = A + (size_t)(by * 128 + arow) * Kd + acol;
    const float* Bptr = B + (size_t)brow * N + bx * 128 + bcol;

    const int tx = tid & 15;
    const int ty = tid >> 4;

    float acc[8][8];
#pragma unroll
    for (int i = 0; i < 8; i++)
#pragma unroll
        for (int j = 0; j < 8; j++) acc[i][j] = 0.f;

    const int nt = Kd >> 3;

    float4 ra = *(const float4*)Aptr;
    float4 rb = *(const float4*)Bptr;
    As[0][acol + 0][arow] = ra.x;
    As[0][acol + 1][arow] = ra.y;
    As[0][acol + 2][arow] = ra.z;
    As[0][acol + 3][arow] = ra.w;
    *(float4*)&Bs[0][brow][bcol] = rb;
    __syncthreads();

    for (int t = 0; t < nt; ++t) {
        const int buf = t & 1;
        if (t + 1 < nt) {
            ra = *(const float4*)(Aptr + (t + 1) * 8);
            rb = *(const float4*)(Bptr + (size_t)(t + 1) * 8 * N);
        }
#pragma unroll
        for (int kk = 0; kk < 8; ++kk) {
            float4 a0 = *(const float4*)&As[buf][kk][ty * 4];
            float4 a1 = *(const float4*)&As[buf][kk][64 + ty * 4];
            float4 b0 = *(const float4*)&Bs[buf][kk][tx * 4];
            float4 b1 = *(const float4*)&Bs[buf][kk][64 + tx * 4];
            float a[8] = {a0.x, a0.y, a0.z, a0.w, a1.x, a1.y, a1.z, a1.w};
            float b[8] = {b0.x, b0.y, b0.z, b0.w, b1.x, b1.y, b1.z, b1.w};
#pragma unroll
            for (int i = 0; i < 8; i++)
#pragma unroll
                for (int j = 0; j < 8; j++)
                    acc[i][j] = fmaf(a[i], b[j], acc[i][j]);
        }
        if (t + 1 < nt) {
            const int nb = buf ^ 1;
            As[nb][acol + 0][arow] = ra.x;
            As[nb][acol + 1][arow] = ra.y;
            As[nb][acol + 2][arow] = ra.z;
            As[nb][acol + 3][arow] = ra.w;
            *(float4*)&Bs[nb][brow][bcol] = rb;
            __syncthreads();
        }
    }

#pragma unroll
    for (int ii = 0; ii < 2; ii++) {
#pragma unroll
        for (int i = 0; i < 4; i++) {
            const int row = by * 128 + ii * 64 + ty * 4 + i;
            float* cp = C + (size_t)row * N + bx * 128;
#pragma unroll
            for (int jj = 0; jj < 2; jj++) {
                const int c0 = jj * 64 + tx * 4;
                float4 v;
                v.x = acc[ii * 4 + i][jj * 4 + 0] + bias[bx * 128 + c0 + 0];
                v.y = acc[ii * 4 + i][jj * 4 + 1] + bias[bx * 128 + c0 + 1];
                v.z = acc[ii * 4 + i][jj * 4 + 2] + bias[bx * 128 + c0 + 2];
                v.w = acc[ii * 4 + i][jj * 4 + 3] + bias[bx * 128 + c0 + 3];
                *(float4*)(cp + c0) = v;
            }
        }
    }
}

// ---------------------------------------------------------------------------
// RoPE in-place on q and k parts of g_qkv.
// rotate_half: out[j]    = x[j]*cos[j]    - x[j+40]*sin[j]      (j <  40)
//              out[j+40] = x[j+40]*cos[j+40] + x[j]*sin[j+40]
// One thread handles one (n, h, j<40) pair for both q and k.
// ---------------------------------------------------------------------------
__global__ __launch_bounds__(256) void rope_kernel(
    const float* __restrict__ cosNK, const float* __restrict__ sinNK)
{
    const int t = blockIdx.x * blockDim.x + threadIdx.x;
    if (t >= NTOK * NH * 40) return;
    const int j = t % 40;
    const int h = (t / 40) % NH;
    const int n = t / (40 * NH);

    const float c1 = cosNK[n * HK + j];
    const float s1 = sinNK[n * HK + j];
    const float c2 = cosNK[n * HK + j + 40];
    const float s2 = sinNK[n * HK + j + 40];

    size_t base = (size_t)n * (3 * DM) + h * HK;
    // q
    {
        float x1 = g_qkv[base + j], x2 = g_qkv[base + j + 40];
        g_qkv[base + j]      = x1 * c1 - x2 * s1;
        g_qkv[base + j + 40] = x2 * c2 + x1 * s2;
    }
    // k
    base += DM;
    {
        float x1 = g_qkv[base + j], x2 = g_qkv[base + j + 40];
        g_qkv[base + j]      = x1 * c1 - x2 * s1;
        g_qkv[base + j + 40] = x2 * c2 + x1 * s2;
    }
}

// ---------------------------------------------------------------------------
// Flash attention (fp32, online softmax).
// Block: one (segment, head, 64-query tile). 256 threads.
// Loops over 2048 keys in chunks of 64. S tile 64x64 (4x4 per thread,
// column-strided by 16 for conflict-free Ks reads), O tile 64x80
// (4x5 per thread). Row reductions via 16-lane shuffle butterflies.
// ---------------------------------------------------------------------------
#define BM 64
#define BN 64
#define QP 81   // pitch for Qs/Ks
#define VP 80   // pitch for Vs
#define PP 65   // pitch for Ps

__global__ __launch_bounds__(256) void attn_kernel(
    const float* __restrict__ qkv, float* __restrict__ ao)
{
    extern __shared__ float sm[];
    float* Qs = sm;                      // 64*81
    float* Ks = Qs + BM * QP;            // 64*81
    float* Vs = Ks + BN * QP;            // 64*80
    float* Ps = Vs + BN * VP;            // 64*65

    const int tid = threadIdx.x;
    const int qt = blockIdx.x, head = blockIdx.y, seg = blockIdx.z;
    const int n0 = seg * SEGL + qt * BM;

    const float scale = 0.1118033988749895f;  // 80^-0.5

    // Load + pre-scale Q tile
    for (int idx = tid; idx < BM * HK; idx += 256) {
        const int r = idx / HK, c = idx % HK;
        Qs[r * QP + c] = qkv[(size_t)(n0 + r) * (3 * DM) + head * HK + c] * scale;
    }

    const int lx = tid & 15;          // col lane (16 lanes per row-group)
    const int row0 = (tid >> 4) * 4;  // 4 query rows per thread

    float acc[4][5];
    float mrow[4], lrow[4];
#pragma unroll
    for (int i = 0; i < 4; i++) {
        mrow[i] = NEG_INF;
        lrow[i] = 0.f;
#pragma unroll
        for (int j = 0; j < 5; j++) acc[i][j] = 0.f;
    }
    __syncthreads();

    for (int kb = 0; kb < SEGL / BN; ++kb) {
        const int nk = seg * SEGL + kb * BN;
        for (int idx = tid; idx < BN * HK; idx += 256) {
            const int r = idx / HK, c = idx % HK;
            const size_t gb = (size_t)(nk + r) * (3 * DM) + head * HK + c;
            Ks[r * QP + c] = qkv[gb + DM];
            Vs[r * VP + c] = qkv[gb + 2 * DM];
        }
        __syncthreads();

        // S = (Q*scale) @ K^T ; thread cols = lx + 16*j
        float s[4][4];
#pragma unroll
        for (int i = 0; i < 4; i++)
#pragma unroll
            for (int j = 0; j < 4; j++) s[i][j] = 0.f;

#pragma unroll 4
        for (int kk = 0; kk < HK; ++kk) {
            float qv[4], kv[4];
#pragma unroll
            for (int i = 0; i < 4; i++) qv[i] = Qs[(row0 + i) * QP + kk];
#pragma unroll
            for (int j = 0; j < 4; j++) kv[j] = Ks[(lx + 16 * j) * QP + kk];
#pragma unroll
            for (int i = 0; i < 4; i++)
#pragma unroll
                for (int j = 0; j < 4; j++)
                    s[i][j] = fmaf(qv[i], kv[j], s[i][j]);
        }

        // Online softmax update per row
#pragma unroll
        for (int i = 0; i < 4; i++) {
            float mi = fmaxf(fmaxf(s[i][0], s[i][1]), fmaxf(s[i][2], s[i][3]));
            mi = fmaxf(mi, __shfl_xor_sync(0xffffffffu, mi, 1));
            mi = fmaxf(mi, __shfl_xor_sync(0xffffffffu, mi, 2));
            mi = fmaxf(mi, __shfl_xor_sync(0xffffffffu, mi, 4));
            mi = fmaxf(mi, __shfl_xor_sync(0xffffffffu, mi, 8));
            const float mnew = fmaxf(mrow[i], mi);
            const float corr = __expf(mrow[i] - mnew);   // exp(-inf)=0 on first iter
            float rs = 0.f;
#pragma unroll
            for (int j = 0; j < 4; j++) {
                s[i][j] = __expf(s[i][j] - mnew);
                rs += s[i][j];
            }
            rs += __shfl_xor_sync(0xffffffffu, rs, 1);
            rs += __shfl_xor_sync(0xffffffffu, rs, 2);
            rs += __shfl_xor_sync(0xffffffffu, rs, 4);
            rs += __shfl_xor_sync(0xffffffffu, rs, 8);
            lrow[i] = lrow[i] * corr + rs;
            mrow[i] = mnew;
#pragma unroll
            for (int c2 = 0; c2 < 5; c2++) acc[i][c2] *= corr;
#pragma unroll
            for (int j = 0; j < 4; j++)
                Ps[(row0 + i) * PP + lx + 16 * j] = s[i][j];
        }
        __syncthreads();

        // O += P @ V ; thread out cols = lx + 16*j (j<5)
#pragma unroll 4
        for (int kk = 0; kk < BN; ++kk) {
            float p[4], vv[5];
#pragma unroll
            for (int i = 0; i < 4; i++) p[i] = Ps[(row0 + i) * PP + kk];
#pragma unroll
            for (int j = 0; j < 5; j++) vv[j] = Vs[kk * VP + lx + 16 * j];
#pragma unroll
            for (int i = 0; i < 4; i++)
#pragma unroll
                for (int j = 0; j < 5; j++)
                    acc[i][j] = fmaf(p[i], vv[j], acc[i][j]);
        }
        __syncthreads();
    }

    // Write normalized output
#pragma unroll
    for (int i = 0; i < 4; i++) {
        const float inv = 1.f / lrow[i];
        float* op = ao + (size_t)(n0 + row0 + i) * DM + head * HK;
#pragma unroll
        for (int j = 0; j < 5; j++)
            op[lx + 16 * j] = acc[i][j] * inv;
    }
}

// ---------------------------------------------------------------------------
// Launch
// ---------------------------------------------------------------------------
extern "C" void kernel_launch(void* const* d_in, const int* in_sizes, int n_in,
                              void* d_out, int out_size)
{
    const float* hidden = (const float*)d_in[0];
    const float* cosNK  = (const float*)d_in[1];
    const float* sinNK  = (const float*)d_in[2];
    const float* qkv_w  = (const float*)d_in[3];
    const float* qkv_b  = (const float*)d_in[4];
    const float* proj_w = (const float*)d_in[5];
    const float* proj_b = (const float*)d_in[6];
    float* out = (float*)d_out;

    float* qkv = nullptr;
    float* ao  = nullptr;
    cudaGetSymbolAddress((void**)&qkv, g_qkv);
    cudaGetSymbolAddress((void**)&ao,  g_ao);

    // Allow >48KB dynamic smem for attention (idempotent; persists across calls)
    const int attn_smem = (BM * QP + BN * QP + BN * VP + BM * PP) * (int)sizeof(float);
    cudaFuncSetAttribute(attn_kernel, cudaFuncAttributeMaxDynamicSharedMemorySize, attn_smem);

    // 1) qkv = hidden @ qkv_w + qkv_b   (16384 x 3840)
    gemm_bias_kernel<<<dim3(3 * DM / 128, NTOK / 128), 256>>>(
        hidden, qkv_w, qkv_b, qkv, NTOK, 3 * DM, DM);

    // 2) RoPE on q,k
    {
        const int total = NTOK * NH * 40;
        rope_kernel<<<(total + 255) / 256, 256>>>(cosNK, sinNK);
    }

    // 3) attention per (segment, head, qtile)
    attn_kernel<<<dim3(SEGL / BM, NH, NSEGS), 256, attn_smem>>>(qkv, ao);

    // 4) out = ao @ proj_w + proj_b   (16384 x 1280)
    gemm_bias_kernel<<<dim3(DM / 128, NTOK / 128), 256>>>(
        ao, proj_w, proj_b, out, NTOK, DM, DM);
}